// round 16
// baseline (speedup 1.0000x reference)
#include <cuda_runtime.h>
#include <cuda_fp16.h>
#include <cstdint>
#include <math.h>

// Problem shape (fixed)
#define BATCH 64
#define LEN   1024
#define DIM   1024
#define HID   1024
#define UNITS 1024
#define MROWS (BATCH * LEN)   // 65536

// fp16 GEMM tiling (mma.sync m16n8k16 f16)
#define BM 128
#define BN 64
#define BKH 64                // halves per k-chunk = 128 bytes/row
#define KT (DIM / BKH)        // 16
#define NTILES (UNITS / BN)   // 16
#define STAGES 3
#define STAGE_A_BYTES (BM * 128)                       // 16384
#define STAGE_B_BYTES (BN * 128)                       // 8192
#define STAGE_BYTES   (STAGE_A_BYTES + STAGE_B_BYTES)  // 24576
#define DYN_SMEM (STAGES * STAGE_BYTES)                // 73728

// Scratch (__device__ globals; no allocation allowed)
__device__ __half g_feat_h[(size_t)MROWS * DIM];    // features in fp16 (128 MB)
__device__ __half g_w1t_h[(size_t)UNITS * DIM];     // W1 transposed [u][d], fp16
__device__ float  g_projh[BATCH * UNITS];           // hidden @ W2 + b2
__device__ float  g_partial[(size_t)MROWS * NTILES];// partial logits per (row, ntile)

// ---------------------------------------------------------------------------
// helpers
// ---------------------------------------------------------------------------
__device__ __forceinline__ uint32_t smem_u32(const void* p) {
    uint32_t a;
    asm("{ .reg .u64 t; cvta.to.shared.u64 t, %1; cvt.u32.u64 %0, t; }" : "=r"(a) : "l"(p));
    return a;
}

__device__ __forceinline__ uint32_t h2_as_u32(__half2 h) {
    return *reinterpret_cast<uint32_t*>(&h);
}

#define CP_ASYNC16(dst, src) \
    asm volatile("cp.async.cg.shared.global [%0], [%1], 16;" :: "r"(dst), "l"(src))
#define CP_COMMIT() asm volatile("cp.async.commit_group;" ::: "memory")
#define CP_WAIT1()  asm volatile("cp.async.wait_group 1;" ::: "memory")
#define CP_WAIT0()  asm volatile("cp.async.wait_group 0;" ::: "memory")

#define LDSM_X4(r, addr)                                                        \
    asm volatile("ldmatrix.sync.aligned.m8n8.x4.shared.b16 {%0,%1,%2,%3}, [%4];" \
                 : "=r"((r)[0]), "=r"((r)[1]), "=r"((r)[2]), "=r"((r)[3])        \
                 : "r"(addr))

__device__ __forceinline__ void mma_f16(float c[4], const uint32_t a[4],
                                        uint32_t b0, uint32_t b1) {
    asm volatile(
        "mma.sync.aligned.m16n8k16.row.col.f32.f16.f16.f32 "
        "{%0,%1,%2,%3}, {%4,%5,%6,%7}, {%8,%9}, {%0,%1,%2,%3};\n"
        : "+f"(c[0]), "+f"(c[1]), "+f"(c[2]), "+f"(c[3])
        : "r"(a[0]), "r"(a[1]), "r"(a[2]), "r"(a[3]), "r"(b0), "r"(b1));
}

__device__ __forceinline__ float tanh_fast(float x) {
    float e = __expf(2.0f * x);
    return 1.0f - __fdividef(2.0f, e + 1.0f);
}

// ---------------------------------------------------------------------------
// 0) Convert features fp32 -> fp16 (rn). 8 floats per thread.
// ---------------------------------------------------------------------------
__global__ __launch_bounds__(256) void conv_feat_kernel(const float* __restrict__ features) {
    size_t i = ((size_t)blockIdx.x * 256 + threadIdx.x) * 8;
    float4 v0 = *(const float4*)(features + i);
    float4 v1 = *(const float4*)(features + i + 4);
    uint4 out;
    out.x = h2_as_u32(__floats2half2_rn(v0.x, v0.y));
    out.y = h2_as_u32(__floats2half2_rn(v0.z, v0.w));
    out.z = h2_as_u32(__floats2half2_rn(v1.x, v1.y));
    out.w = h2_as_u32(__floats2half2_rn(v1.z, v1.w));
    *(uint4*)(g_feat_h + i) = out;
}

// ---------------------------------------------------------------------------
// 1) Transpose W1 [D][U] -> g_w1t_h [U][D], fp16 (rn)
// ---------------------------------------------------------------------------
__global__ void prep_w1_kernel(const float* __restrict__ W1) {
    __shared__ float tile[32][33];
    int u = blockIdx.x * 32 + threadIdx.x;
    int d0 = blockIdx.y * 32;
#pragma unroll
    for (int j = 0; j < 32; j += 8)
        tile[threadIdx.y + j][threadIdx.x] = W1[(size_t)(d0 + threadIdx.y + j) * UNITS + u];
    __syncthreads();
    int dd = d0 + threadIdx.x;
    int u0 = blockIdx.x * 32;
#pragma unroll
    for (int j = 0; j < 32; j += 8)
        g_w1t_h[(size_t)(u0 + threadIdx.y + j) * DIM + dd] =
            __float2half_rn(tile[threadIdx.x][threadIdx.y + j]);
}

// ---------------------------------------------------------------------------
// 2) proj_h = hidden @ W2 + b2 — tiled so W2 is read exactly once (fp32 exact)
// ---------------------------------------------------------------------------
__global__ __launch_bounds__(512) void projh_kernel(const float* __restrict__ hidden,
                                                    const float* __restrict__ W2,
                                                    const float* __restrict__ b2) {
    __shared__ float sh[64][65];
    __shared__ float sw[64][65];
    const int tid = threadIdx.x;
    const int u0 = blockIdx.x * 64;
    const int uu = tid & 63;
    const int bb = (tid >> 6) * 8;
    float acc[8] = {0.f, 0.f, 0.f, 0.f, 0.f, 0.f, 0.f, 0.f};

    for (int hc = 0; hc < HID / 64; hc++) {
        const int h0 = hc * 64;
#pragma unroll
        for (int i = 0; i < 8; i++) {
            int idx = tid + i * 512;
            int b = idx >> 6, h = idx & 63;
            sh[b][h] = hidden[(size_t)b * HID + h0 + h];
        }
#pragma unroll
        for (int i = 0; i < 8; i++) {
            int idx = tid + i * 512;
            int h = idx >> 6, u = idx & 63;
            sw[h][u] = W2[(size_t)(h0 + h) * UNITS + u0 + u];
        }
        __syncthreads();
#pragma unroll 16
        for (int h = 0; h < 64; h++) {
            float w = sw[h][uu];
#pragma unroll
            for (int j = 0; j < 8; j++)
                acc[j] += sh[bb + j][h] * w;
        }
        __syncthreads();
    }
    float bias = b2[u0 + uu];
#pragma unroll
    for (int j = 0; j < 8; j++)
        g_projh[(size_t)(bb + j) * UNITS + u0 + uu] = acc[j] + bias;
}

// ---------------------------------------------------------------------------
// 3) Fused fp16 GEMM: cp.async 3-stage, 128 threads, 3 CTAs/SM
//    grid (NTILES, MROWS/BM) = (16, 512); 4 warps (2m x 2n), warp tile 64x32
//    Three independent CTAs per SM -> deeper LDSM/MMA interleave
// ---------------------------------------------------------------------------
__global__ __launch_bounds__(128, 3) void fused_gemm_f16(const float* __restrict__ b1,
                                                         const float* __restrict__ V) {
    extern __shared__ char dsmem_raw[];
    __shared__ float s_red[2][BM];
    __shared__ float s_add[BN];
    __shared__ float s_v[BN];

    const int tid  = threadIdx.x;
    const int lane = tid & 31;
    const int warp = tid >> 5;          // 0..3
    const int wm   = warp >> 1;         // 0..1
    const int wn   = warp & 1;          // 0..1
    const int ntile = blockIdx.x;
    const int mtile = blockIdx.y;
    const size_t row0 = (size_t)mtile * BM;
    const int u0 = ntile * BN;
    const int b = mtile >> 3;           // LEN/BM = 8 m-tiles per batch

    const uint32_t smem0 = smem_u32(dsmem_raw);

    if (tid < BN) {
        s_add[tid] = g_projh[(size_t)b * UNITS + u0 + tid] + b1[u0 + tid];
        s_v[tid]   = V[u0 + tid];
    }

    float acc[4][4][4];
#pragma unroll
    for (int mi = 0; mi < 4; mi++)
#pragma unroll
        for (int ni = 0; ni < 4; ni++)
#pragma unroll
            for (int j = 0; j < 4; j++) acc[mi][ni][j] = 0.f;

    const __half* Ag = g_feat_h + row0 * DIM;
    const __half* Bg = g_w1t_h + (size_t)u0 * DIM;

    // loader constants (128 threads, 8 threads/row of 128B, 16B each)
    const int lrow  = tid >> 3;                // 0..15
    const int lcolh = (tid & 7) * 8;           // half-index within row
    const uint32_t lsw = ((uint32_t)(tid & 7) * 16) ^ ((uint32_t)(lrow & 7) << 4);

    // ldmatrix per-lane constants (b16 fragments, 128B rows)
    const uint32_t aRow  = (uint32_t)(wm * 64 + (lane & 7) + ((lane >> 3) & 1) * 8);
    const uint32_t aColB = (uint32_t)(lane >> 4) * 16;
    const uint32_t bRow  = (uint32_t)(wn * 32 + (lane & 7) + (lane >> 4) * 8);
    const uint32_t bColB = (uint32_t)((lane >> 3) & 1) * 16;

    auto load_stage = [&](int itL, int slot) {
        const uint32_t sA = smem0 + slot * STAGE_BYTES;
        const uint32_t sB = sA + STAGE_A_BYTES;
        const int k0 = itL * BKH;
#pragma unroll
        for (int p = 0; p < 8; p++) {          // A: 128 rows
            int r = lrow + p * 16;
            CP_ASYNC16(sA + (uint32_t)r * 128 + lsw, Ag + (size_t)r * DIM + k0 + lcolh);
        }
#pragma unroll
        for (int p = 0; p < 4; p++) {          // B: 64 rows
            int r = lrow + p * 16;
            CP_ASYNC16(sB + (uint32_t)r * 128 + lsw, Bg + (size_t)r * DIM + k0 + lcolh);
        }
    };

    load_stage(0, 0); CP_COMMIT();
    load_stage(1, 1); CP_COMMIT();

#pragma unroll 1
    for (int it = 0; it < KT; it++) {
        CP_WAIT1();          // stage `it` resident (<=1 newer group outstanding)
        __syncthreads();

        const int ls = it + STAGES - 1;
        const int lslot = (it + 2) % STAGES;
        if (ls < KT) load_stage(ls, lslot);
        CP_COMMIT();         // uniform group counting

        const uint32_t sA = smem0 + (it % STAGES) * STAGE_BYTES;
        const uint32_t sB = sA + STAGE_A_BYTES;
#pragma unroll
        for (int ks = 0; ks < 4; ks++) {       // k16 per step, 64 per chunk
            const uint32_t kb = (uint32_t)(ks * 32);  // byte offset of k-step
            uint32_t afr[4][4];
#pragma unroll
            for (int mi = 0; mi < 4; mi++) {
                uint32_t r = aRow + (uint32_t)mi * 16;
                LDSM_X4(afr[mi], sA + r * 128 + ((kb + aColB) ^ ((r & 7) << 4)));
            }
            uint32_t bfr[2][4];
#pragma unroll
            for (int p = 0; p < 2; p++) {
                uint32_t r = bRow + (uint32_t)p * 16;
                LDSM_X4(bfr[p], sB + r * 128 + ((kb + bColB) ^ ((r & 7) << 4)));
            }
#pragma unroll
            for (int mi = 0; mi < 4; mi++) {
#pragma unroll
                for (int p = 0; p < 2; p++) {
                    mma_f16(acc[mi][2 * p],     afr[mi], bfr[p][0], bfr[p][1]);
                    mma_f16(acc[mi][2 * p + 1], afr[mi], bfr[p][2], bfr[p][3]);
                }
            }
        }
    }
    CP_WAIT0();

    // ---- epilogue: tanh(acc + proj_h + b1) . V, reduce over BN ----
#pragma unroll
    for (int mi = 0; mi < 4; mi++) {
        float sum0 = 0.f, sum1 = 0.f;
#pragma unroll
        for (int ni = 0; ni < 4; ni++) {
            int c = wn * 32 + ni * 8 + 2 * (lane & 3);
            float add0 = s_add[c], add1 = s_add[c + 1];
            float v0 = s_v[c], v1 = s_v[c + 1];
            sum0 += v0 * tanh_fast(acc[mi][ni][0] + add0) + v1 * tanh_fast(acc[mi][ni][1] + add1);
            sum1 += v0 * tanh_fast(acc[mi][ni][2] + add0) + v1 * tanh_fast(acc[mi][ni][3] + add1);
        }
        sum0 += __shfl_xor_sync(0xffffffff, sum0, 1);
        sum0 += __shfl_xor_sync(0xffffffff, sum0, 2);
        sum1 += __shfl_xor_sync(0xffffffff, sum1, 1);
        sum1 += __shfl_xor_sync(0xffffffff, sum1, 2);
        if ((lane & 3) == 0) {
            int r = wm * 64 + mi * 16 + (lane >> 2);
            s_red[wn][r]     = sum0;
            s_red[wn][r + 8] = sum1;
        }
    }
    __syncthreads();
    if (tid < BM) {
        float part = s_red[0][tid] + s_red[1][tid];
        g_partial[(row0 + tid) * NTILES + ntile] = part;
    }
}

// ---------------------------------------------------------------------------
// 4) Softmax over L per batch (16 partials per row now)
// ---------------------------------------------------------------------------
__global__ __launch_bounds__(256) void softmax_kernel(const float* __restrict__ bV,
                                                      float* __restrict__ out_w) {
    __shared__ float sl[LEN];
    __shared__ float sred[256];
    int b = blockIdx.x, tid = threadIdx.x;
    float bv = bV[0];
    float lmax = -1e30f;
    for (int i = tid; i < LEN; i += 256) {
        const float* p = g_partial + (size_t)(b * LEN + i) * NTILES;
        float s = (((p[0] + p[1]) + (p[2] + p[3])) + ((p[4] + p[5]) + (p[6] + p[7]))) +
                  (((p[8] + p[9]) + (p[10] + p[11])) + ((p[12] + p[13]) + (p[14] + p[15]))) + bv;
        sl[i] = s;
        lmax = fmaxf(lmax, s);
    }
    sred[tid] = lmax;
    __syncthreads();
    for (int s = 128; s > 0; s >>= 1) {
        if (tid < s) sred[tid] = fmaxf(sred[tid], sred[tid + s]);
        __syncthreads();
    }
    float mx = sred[0];
    __syncthreads();
    float lsum = 0.f;
    for (int i = tid; i < LEN; i += 256) {
        float e = expf(sl[i] - mx);
        sl[i] = e;
        lsum += e;
    }
    sred[tid] = lsum;
    __syncthreads();
    for (int s = 128; s > 0; s >>= 1) {
        if (tid < s) sred[tid] += sred[tid + s];
        __syncthreads();
    }
    float inv = 1.0f / sred[0];
    for (int i = tid; i < LEN; i += 256)
        out_w[(size_t)b * LEN + i] = sl[i] * inv;
}

// ---------------------------------------------------------------------------
// 5) context[b][d] = sum_l w[b][l] * features[b][l][d]  (fp16 features, half2)
// ---------------------------------------------------------------------------
__global__ __launch_bounds__(256) void context_kernel(const float* __restrict__ w,
                                                      float* __restrict__ out) {
    __shared__ float sw[LEN];
    int b = blockIdx.y, chunk = blockIdx.x, tid = threadIdx.x;
    for (int i = tid; i < LEN; i += 256) sw[i] = w[(size_t)b * LEN + i];
    __syncthreads();
    int d = (chunk * 256 + tid) * 2;
    const __half2* f = (const __half2*)(g_feat_h + (size_t)b * LEN * DIM + d);
    float ax0 = 0.f, ay0 = 0.f, ax1 = 0.f, ay1 = 0.f;
    for (int l = 0; l < LEN; l += 2) {
        float2 v0 = __half22float2(f[(size_t)l * (DIM / 2)]);
        float2 v1 = __half22float2(f[(size_t)(l + 1) * (DIM / 2)]);
        ax0 += sw[l] * v0.x;     ay0 += sw[l] * v0.y;
        ax1 += sw[l + 1] * v1.x; ay1 += sw[l + 1] * v1.y;
    }
    out[(size_t)b * DIM + d]     = ax0 + ax1;
    out[(size_t)b * DIM + d + 1] = ay0 + ay1;
}

// ---------------------------------------------------------------------------
extern "C" void kernel_launch(void* const* d_in, const int* in_sizes, int n_in,
                              void* d_out, int out_size) {
    const float* features = (const float*)d_in[0];
    const float* hidden   = (const float*)d_in[1];
    const float* W1       = (const float*)d_in[2];
    const float* b1       = (const float*)d_in[3];
    const float* W2       = (const float*)d_in[4];
    const float* b2       = (const float*)d_in[5];
    const float* V        = (const float*)d_in[6];
    const float* bV       = (const float*)d_in[7];

    float* out_ctx = (float*)d_out;                 // [B, D]
    float* out_w   = (float*)d_out + BATCH * DIM;   // [B, L, 1]

    static bool attr_set = false;
    if (!attr_set) {
        cudaFuncSetAttribute(fused_gemm_f16, cudaFuncAttributeMaxDynamicSharedMemorySize, DYN_SMEM);
        attr_set = true;
    }

    conv_feat_kernel<<<(MROWS * (DIM / 8)) / 256, 256>>>(features);
    prep_w1_kernel<<<dim3(32, 32), dim3(32, 8)>>>(W1);
    projh_kernel<<<UNITS / 64, 512>>>(hidden, W2, b2);
    fused_gemm_f16<<<dim3(NTILES, MROWS / BM), 128, DYN_SMEM>>>(b1, V);
    softmax_kernel<<<BATCH, 256>>>(bV, out_w);
    context_kernel<<<dim3(DIM / 512, BATCH), 256>>>(out_w, out_ctx);
}